// round 1
// baseline (speedup 1.0000x reference)
#include <cuda_runtime.h>
#include <math.h>

// ---------------- problem constants ----------------
#define BB    2
#define TT    2048
#define DIM   1024
#define NTOK  4096          // BB*TT
#define HEADS 16
#define HD    64
#define NEXP  8
#define HID   4096
#define MAXTOK 4096         // per-expert capacity (worst case)

// ---------------- device scratch (static, allowed) ----------------
__device__ float g_h   [NTOK * DIM];                 // ln1 out
__device__ float g_qkv [NTOK * 3 * DIM];             // qkv
__device__ float g_y   [NTOK * DIM];                 // attn out
__device__ float g_x1  [NTOK * DIM];                 // x + attn proj
__device__ float g_h2  [NTOK * DIM];                 // ln2 out
__device__ float g_hid [(size_t)NTOK * 2 * HID];     // gathered expert hidden pool (8192 rows)
__device__ float g_c   [2][NTOK * DIM];              // per-slot MoE contributions
__device__ int   g_cnt [NEXP];
__device__ int   g_base[NEXP];
__device__ int   g_tok [NEXP * MAXTOK];
__device__ float g_wt  [NEXP * MAXTOK];
__device__ int   g_slot[NEXP * MAXTOK];

// ---------------- tiny utility kernels ----------------
__global__ void zero_cnt_kernel() {
    if (threadIdx.x < NEXP) g_cnt[threadIdx.x] = 0;
}

__global__ void base_kernel() {
    if (threadIdx.x == 0) {
        int s = 0;
        for (int e = 0; e < NEXP; ++e) { g_base[e] = s; s += g_cnt[e]; }
    }
}

__global__ void final_kernel(float* __restrict__ out) {
    int i = blockIdx.x * 256 + threadIdx.x;
    out[i] = g_x1[i] + g_c[0][i] + g_c[1][i];
}

// ---------------- layernorm: one block (256 thr) per token ----------------
__global__ void ln_kernel(const float* __restrict__ in, const float* __restrict__ gam,
                          const float* __restrict__ bet, float* __restrict__ out) {
    __shared__ float sx[DIM];
    __shared__ float red[8];
    const int n = blockIdx.x, tid = threadIdx.x;
    const float* row = in + (size_t)n * DIM;

    float s = 0.f;
    // DIM/4 = 256 float4 -> one per thread
    {
        float4 x4 = ((const float4*)row)[tid];
        ((float4*)sx)[tid] = x4;
        s = x4.x + x4.y + x4.z + x4.w;
    }
    #pragma unroll
    for (int o = 16; o; o >>= 1) s += __shfl_xor_sync(~0u, s, o);
    if ((tid & 31) == 0) red[tid >> 5] = s;
    __syncthreads();
    float mu;
    {
        float t = (tid < 8) ? red[tid & 7] : 0.f; // all threads compute same
        // serialize tiny reduce: just have every thread sum 8 slots
        t = red[0] + red[1] + red[2] + red[3] + red[4] + red[5] + red[6] + red[7];
        mu = t * (1.0f / DIM);
    }
    float sq = 0.f;
    #pragma unroll
    for (int p = 0; p < 4; ++p) {
        float d = sx[tid + p * 256] - mu;
        sq += d * d;
    }
    #pragma unroll
    for (int o = 16; o; o >>= 1) sq += __shfl_xor_sync(~0u, sq, o);
    __syncthreads();
    if ((tid & 31) == 0) red[tid >> 5] = sq;
    __syncthreads();
    float var = (red[0] + red[1] + red[2] + red[3] + red[4] + red[5] + red[6] + red[7]) * (1.0f / DIM);
    float rs = rsqrtf(var + 1e-5f);
    float* orow = out + (size_t)n * DIM;
    #pragma unroll
    for (int p = 0; p < 4; ++p) {
        int d = tid + p * 256;
        orow[d] = (sx[d] - mu) * rs * gam[d] + bet[d];
    }
}

// ---------------- SGEMM: 128x128x8 tile, 8x8 micro-tile, 256 threads ----------------
// MODE 0: C = A @ B                               (qkv)
// MODE 1: C = aux + A @ B                         (proj + residual)
// MODE 2: per-expert gather-GEMM + bias + GELU    (moe up)
// MODE 3: per-expert GEMM + bias, scaled scatter  (moe down)
template <int MODE>
__global__ void __launch_bounds__(256)
gemm_kernel(const float* __restrict__ A, const float* __restrict__ Bm,
            float* __restrict__ C, int M, int N, int K,
            const float* __restrict__ aux) {
    const int e = (MODE >= 2) ? blockIdx.z : 0;
    int Mrows = M;
    const float* Bp = Bm;
    const float* Ap = A;
    const float* bias = aux;
    int pbase = 0;

    if (MODE == 2) {
        Mrows = g_cnt[e];
        if ((int)blockIdx.y * 128 >= Mrows) return;
        Bp = Bm + (size_t)e * K * N;
        bias = aux + (size_t)e * N;
        pbase = g_base[e];
    } else if (MODE == 3) {
        Mrows = g_cnt[e];
        if ((int)blockIdx.y * 128 >= Mrows) return;
        Ap = A + (size_t)g_base[e] * K;
        Bp = Bm + (size_t)e * K * N;
        bias = aux + (size_t)e * N;
    }

    __shared__ __align__(16) float As[8][128];
    __shared__ __align__(16) float Bs[8][128];

    float acc[8][8];
    #pragma unroll
    for (int i = 0; i < 8; ++i)
        #pragma unroll
        for (int j = 0; j < 8; ++j) acc[i][j] = 0.f;

    const int tid = threadIdx.x;
    const int tx = tid & 15, ty = tid >> 4;
    const int m0 = blockIdx.y * 128, n0 = blockIdx.x * 128;
    const int a_m = tid >> 1, a_k = (tid & 1) * 4;
    const int b_k = tid >> 5, b_n = (tid & 31) * 4;

    const float* a_src = nullptr;
    {
        int mm = m0 + a_m;
        if (mm < Mrows) {
            if (MODE == 2) a_src = A + (size_t)g_tok[e * MAXTOK + mm] * K;
            else           a_src = Ap + (size_t)mm * K;
        }
    }
    const float* b_src = Bp + (size_t)b_k * N + n0 + b_n;

    const int nk = K >> 3;
    for (int kt = 0; kt < nk; ++kt) {
        float4 av = make_float4(0.f, 0.f, 0.f, 0.f);
        if (a_src) av = *(const float4*)(a_src + kt * 8 + a_k);
        float4 bv = *(const float4*)(b_src + (size_t)kt * 8 * N);
        As[a_k + 0][a_m] = av.x;
        As[a_k + 1][a_m] = av.y;
        As[a_k + 2][a_m] = av.z;
        As[a_k + 3][a_m] = av.w;
        *(float4*)&Bs[b_k][b_n] = bv;
        __syncthreads();
        #pragma unroll
        for (int kk = 0; kk < 8; ++kk) {
            float4 a0 = *(const float4*)&As[kk][ty * 8];
            float4 a1 = *(const float4*)&As[kk][ty * 8 + 4];
            float4 c0 = *(const float4*)&Bs[kk][tx * 8];
            float4 c1 = *(const float4*)&Bs[kk][tx * 8 + 4];
            float ar[8] = {a0.x, a0.y, a0.z, a0.w, a1.x, a1.y, a1.z, a1.w};
            float br[8] = {c0.x, c0.y, c0.z, c0.w, c1.x, c1.y, c1.z, c1.w};
            #pragma unroll
            for (int i = 0; i < 8; ++i)
                #pragma unroll
                for (int j = 0; j < 8; ++j) acc[i][j] += ar[i] * br[j];
        }
        __syncthreads();
    }

    #pragma unroll
    for (int i = 0; i < 8; ++i) {
        const int m = m0 + ty * 8 + i;
        if (MODE >= 2 && m >= Mrows) continue;
        const int col0 = n0 + tx * 8;
        if (MODE == 0) {
            float* dst = C + (size_t)m * N + col0;
            #pragma unroll
            for (int j = 0; j < 8; ++j) dst[j] = acc[i][j];
        } else if (MODE == 1) {
            const float* r = aux + (size_t)m * N + col0;
            float* dst = C + (size_t)m * N + col0;
            #pragma unroll
            for (int j = 0; j < 8; ++j) dst[j] = r[j] + acc[i][j];
        } else if (MODE == 2) {
            float* dst = C + (size_t)(pbase + m) * N + col0;
            #pragma unroll
            for (int j = 0; j < 8; ++j) {
                float v = acc[i][j] + bias[col0 + j];
                dst[j] = 0.5f * v * (1.f + erff(v * 0.70710678118654752f));
            }
        } else { // MODE 3
            const int t = g_tok[e * MAXTOK + m];
            const float w = g_wt[e * MAXTOK + m];
            const int s = g_slot[e * MAXTOK + m];
            float* dst = &g_c[s][(size_t)t * DIM + col0];
            #pragma unroll
            for (int j = 0; j < 8; ++j) dst[j] = w * (acc[i][j] + bias[col0 + j]);
        }
    }
}

// ---------------- flash attention: 64 q rows x 64 kv per tile ----------------
__global__ void __launch_bounds__(256)
attn_kernel(const float* __restrict__ qkv, float* __restrict__ y) {
    __shared__ __align__(16) float sQ[64][64];   // [d][r], pre-scaled by 1/8
    __shared__ __align__(16) float sKP[64][64];  // [d][j] as K, then [j][r] as P
    __shared__ __align__(16) float sV[64][64];   // [j][d]

    const int qt = blockIdx.x, bh = blockIdx.y;
    const int b = bh >> 4, h = bh & 15;
    const int tid = threadIdx.x, tx = tid & 15, ty = tid >> 4;
    const int qbase = qt * 64;

    // load Q transposed, pre-scaled
    #pragma unroll
    for (int p = 0; p < 4; ++p) {
        int v = tid + p * 256;
        int r = v >> 4, d4 = (v & 15) * 4;
        float4 q4 = *(const float4*)(qkv + (size_t)(b * TT + qbase + r) * (3 * DIM) + h * HD + d4);
        sQ[d4 + 0][r] = q4.x * 0.125f;
        sQ[d4 + 1][r] = q4.y * 0.125f;
        sQ[d4 + 2][r] = q4.z * 0.125f;
        sQ[d4 + 3][r] = q4.w * 0.125f;
    }

    float m_i[4], l_i[4], O[4][4];
    #pragma unroll
    for (int i = 0; i < 4; ++i) {
        m_i[i] = -1e30f; l_i[i] = 0.f;
        #pragma unroll
        for (int j = 0; j < 4; ++j) O[i][j] = 0.f;
    }

    for (int kb = 0; kb <= qt; ++kb) {
        const int kbase = kb * 64;
        __syncthreads();  // previous iteration fully consumed sKP / sV
        #pragma unroll
        for (int p = 0; p < 4; ++p) {
            int v = tid + p * 256;
            int j = v >> 4, d4 = (v & 15) * 4;
            size_t base = (size_t)(b * TT + kbase + j) * (3 * DIM) + h * HD + d4;
            float4 k4 = *(const float4*)(qkv + base + DIM);
            sKP[d4 + 0][j] = k4.x;
            sKP[d4 + 1][j] = k4.y;
            sKP[d4 + 2][j] = k4.z;
            sKP[d4 + 3][j] = k4.w;
            float4 v4 = *(const float4*)(qkv + base + 2 * DIM);
            *(float4*)&sV[j][d4] = v4;
        }
        __syncthreads();

        // S = Q K^T (tile) in registers
        float s[4][4];
        #pragma unroll
        for (int i = 0; i < 4; ++i)
            #pragma unroll
            for (int j = 0; j < 4; ++j) s[i][j] = 0.f;
        #pragma unroll 4
        for (int d = 0; d < 64; ++d) {
            float4 a  = *(const float4*)&sQ[d][ty * 4];
            float4 bk = *(const float4*)&sKP[d][tx * 4];
            float ar[4] = {a.x, a.y, a.z, a.w};
            float br[4] = {bk.x, bk.y, bk.z, bk.w};
            #pragma unroll
            for (int i = 0; i < 4; ++i)
                #pragma unroll
                for (int j = 0; j < 4; ++j) s[i][j] += ar[i] * br[j];
        }
        if (kb == qt) {
            #pragma unroll
            for (int i = 0; i < 4; ++i)
                #pragma unroll
                for (int j = 0; j < 4; ++j)
                    if (tx * 4 + j > ty * 4 + i) s[i][j] = -1e30f;
        }

        float corr[4], p_[4][4];
        #pragma unroll
        for (int i = 0; i < 4; ++i) {
            float mt = fmaxf(fmaxf(s[i][0], s[i][1]), fmaxf(s[i][2], s[i][3]));
            #pragma unroll
            for (int o = 8; o; o >>= 1) mt = fmaxf(mt, __shfl_xor_sync(~0u, mt, o, 16));
            float mn = fmaxf(m_i[i], mt);
            corr[i] = __expf(m_i[i] - mn);
            m_i[i] = mn;
            float rsum = 0.f;
            #pragma unroll
            for (int j = 0; j < 4; ++j) {
                p_[i][j] = __expf(s[i][j] - mn);
                rsum += p_[i][j];
            }
            #pragma unroll
            for (int o = 8; o; o >>= 1) rsum += __shfl_xor_sync(~0u, rsum, o, 16);
            l_i[i] = l_i[i] * corr[i] + rsum;
        }

        __syncthreads();  // done reading sKP as K
        #pragma unroll
        for (int i = 0; i < 4; ++i)
            #pragma unroll
            for (int j = 0; j < 4; ++j)
                sKP[tx * 4 + j][ty * 4 + i] = p_[i][j];   // P^T: [j][r]
        __syncthreads();

        #pragma unroll
        for (int i = 0; i < 4; ++i)
            #pragma unroll
            for (int j = 0; j < 4; ++j) O[i][j] *= corr[i];
        #pragma unroll 4
        for (int jj = 0; jj < 64; ++jj) {
            float4 a  = *(const float4*)&sKP[jj][ty * 4];
            float4 vv = *(const float4*)&sV[jj][tx * 4];
            float ar[4] = {a.x, a.y, a.z, a.w};
            float br[4] = {vv.x, vv.y, vv.z, vv.w};
            #pragma unroll
            for (int i = 0; i < 4; ++i)
                #pragma unroll
                for (int j = 0; j < 4; ++j) O[i][j] += ar[i] * br[j];
        }
    }

    #pragma unroll
    for (int i = 0; i < 4; ++i) {
        float inv = 1.f / l_i[i];
        float4 o4 = make_float4(O[i][0] * inv, O[i][1] * inv, O[i][2] * inv, O[i][3] * inv);
        *(float4*)(y + (size_t)(b * TT + qbase + ty * 4 + i) * DIM + h * HD + tx * 4) = o4;
    }
}

// ---------------- router: one block (128 thr) per token ----------------
__global__ void router_kernel(const float* __restrict__ h2, const float* __restrict__ wr) {
    const int n = blockIdx.x, tid = threadIdx.x;
    float acc[NEXP];
    #pragma unroll
    for (int e = 0; e < NEXP; ++e) acc[e] = 0.f;
    const float* row = h2 + (size_t)n * DIM;
    for (int d = tid; d < DIM; d += 128) {
        float hv = row[d];
        #pragma unroll
        for (int e = 0; e < NEXP; ++e) acc[e] += hv * wr[d * NEXP + e];
    }
    __shared__ float sm[4][NEXP];
    #pragma unroll
    for (int e = 0; e < NEXP; ++e) {
        float v = acc[e];
        #pragma unroll
        for (int o = 16; o; o >>= 1) v += __shfl_xor_sync(~0u, v, o);
        if ((tid & 31) == 0) sm[tid >> 5][e] = v;
    }
    __syncthreads();
    if (tid == 0) {
        float lg[NEXP];
        #pragma unroll
        for (int e = 0; e < NEXP; ++e) lg[e] = sm[0][e] + sm[1][e] + sm[2][e] + sm[3][e];
        int e0 = 0;
        #pragma unroll
        for (int e = 1; e < NEXP; ++e) if (lg[e] > lg[e0]) e0 = e;
        int e1 = -1;
        #pragma unroll
        for (int e = 0; e < NEXP; ++e)
            if (e != e0 && (e1 < 0 || lg[e] > lg[e1])) e1 = e;
        float w0 = 1.f / (1.f + __expf(lg[e1] - lg[e0]));
        float w1 = 1.f - w0;
        int p0 = atomicAdd(&g_cnt[e0], 1);
        g_tok[e0 * MAXTOK + p0] = n; g_wt[e0 * MAXTOK + p0] = w0; g_slot[e0 * MAXTOK + p0] = 0;
        int p1 = atomicAdd(&g_cnt[e1], 1);
        g_tok[e1 * MAXTOK + p1] = n; g_wt[e1 * MAXTOK + p1] = w1; g_slot[e1 * MAXTOK + p1] = 1;
    }
}

// ---------------- launch ----------------
extern "C" void kernel_launch(void* const* d_in, const int* in_sizes, int n_in,
                              void* d_out, int out_size) {
    const float* x        = (const float*)d_in[0];
    const float* ln1_g    = (const float*)d_in[1];
    const float* ln1_b    = (const float*)d_in[2];
    const float* w_attn   = (const float*)d_in[3];
    const float* w_proj   = (const float*)d_in[4];
    const float* ln2_g    = (const float*)d_in[5];
    const float* ln2_b    = (const float*)d_in[6];
    const float* w_router = (const float*)d_in[7];
    const float* w1       = (const float*)d_in[8];
    const float* b1       = (const float*)d_in[9];
    const float* w2       = (const float*)d_in[10];
    const float* b2       = (const float*)d_in[11];
    float* out = (float*)d_out;

    float *p_h, *p_qkv, *p_y, *p_x1, *p_h2, *p_hid;
    cudaGetSymbolAddress((void**)&p_h,   g_h);
    cudaGetSymbolAddress((void**)&p_qkv, g_qkv);
    cudaGetSymbolAddress((void**)&p_y,   g_y);
    cudaGetSymbolAddress((void**)&p_x1,  g_x1);
    cudaGetSymbolAddress((void**)&p_h2,  g_h2);
    cudaGetSymbolAddress((void**)&p_hid, g_hid);

    zero_cnt_kernel<<<1, 32>>>();
    ln_kernel<<<NTOK, 256>>>(x, ln1_g, ln1_b, p_h);

    // qkv = h @ w_attn : [4096,1024]x[1024,3072]
    gemm_kernel<0><<<dim3(3 * DIM / 128, NTOK / 128), 256>>>(p_h, w_attn, p_qkv,
                                                             NTOK, 3 * DIM, DIM, nullptr);
    // attention
    attn_kernel<<<dim3(TT / 64, BB * HEADS), 256>>>(p_qkv, p_y);

    // x1 = x + y @ w_proj
    gemm_kernel<1><<<dim3(DIM / 128, NTOK / 128), 256>>>(p_y, w_proj, p_x1,
                                                         NTOK, DIM, DIM, x);
    // ln2
    ln_kernel<<<NTOK, 256>>>(p_x1, ln2_g, ln2_b, p_h2);

    // routing
    router_kernel<<<NTOK, 128>>>(p_h2, w_router);
    base_kernel<<<1, 32>>>();

    // MoE up: gathered rows of h2 -> gelu(h2 @ w1[e] + b1[e])
    gemm_kernel<2><<<dim3(HID / 128, NTOK / 128, NEXP), 256>>>(p_h2, w1, p_hid,
                                                               NTOK, HID, DIM, b1);
    // MoE down: hid @ w2[e] + b2[e], scaled scatter into g_c[slot]
    gemm_kernel<3><<<dim3(DIM / 128, NTOK / 128, NEXP), 256>>>(p_hid, w2, nullptr,
                                                               NTOK, DIM, HID, b2);
    // out = x1 + c0 + c1
    final_kernel<<<NTOK * DIM / 256, 256>>>(out);
}